// round 7
// baseline (speedup 1.0000x reference)
#include <cuda_runtime.h>
#include <cuda_fp16.h>

#define BATCH 4096
#define LSQ   64
#define HID   64
#define NFLD  11
#define LN    32
#define SROWS 16            // rows per seq CTA
#define SEQ_CTAS ((2 * BATCH) / SROWS)   // 512
#define NWF_ROWS 256        // rows per nwf CTA
#define NWF_CTAS (NFLD * (BATCH / NWF_ROWS))  // 176

// ---------------- scratch (no allocations allowed) ----------------
__device__ float g_m[2 * BATCH * HID];      // [from rows 0..4095 | to rows 4096..8191] x 64
__device__ float g_nwf[NFLD * BATCH * 8];   // [11][4096][8]

__constant__ int c_fm[11] = {0, 0, 1, 1, 2, 2, 3, 3, 4, 5, 5};

__device__ __forceinline__ float tanh_hw(float x) {
    float y; asm("tanh.approx.f32 %0, %1;" : "=f"(y) : "f"(x)); return y;
}
__device__ __forceinline__ float sig_hw(float x) {
    return fmaf(tanh_hw(0.5f * x), 0.5f, 0.5f);
}

// smem overlay: seq role needs 10.7KB, nwf role 2.2KB -> union sized by seq
struct SeqS {
    __half  hbuf[2][SROWS][88];   // cols 0-63 h, 64-69 emb, 70 = 1.0, 71-79 = 0
    int     tok[SROWS][LSQ];
    __half2 ebase[85][3];
};
struct NwfS {
    float wx[256];
    float wh[256];
    float bs[32];
};

// ================= fused kernel: seq CTAs + nwf CTAs =================
__global__ void __launch_bounds__(256, 3) k_main(
    const int* __restrict__ from_seq, const int* __restrict__ to_seq,
    const float* __restrict__ Wh, const float* __restrict__ Wx,
    const float* __restrict__ bias, const float* __restrict__ base_emb,
    const int* __restrict__ nums_g, const int* __restrict__ frs_g,
    const float* __restrict__ ne_g, const float* __restrict__ fe_g,
    const float* __restrict__ nWx_g, const float* __restrict__ nWh_g,
    const float* __restrict__ nb_g)
{
    __shared__ alignas(16) char sraw[sizeof(SeqS)];
    const int tid = threadIdx.x;

    if (blockIdx.x < SEQ_CTAS) {
        // ---------------- seq role: tensor-core LSTM, x folded into MMA (K=80) ----------------
        SeqS* ss = reinterpret_cast<SeqS*>(sraw);
        const int lane = tid & 31;
        const int w    = tid >> 5;
        const int gid  = lane >> 2;
        const int tig  = lane & 3;
        const int row0 = blockIdx.x * SROWS;

        const int* seq = (row0 < BATCH) ? (from_seq + row0 * LSQ)
                                        : (to_seq + (row0 - BATCH) * LSQ);
        for (int i = tid; i < SROWS * LSQ; i += 256) ss->tok[i >> 6][i & 63] = seq[i];
        for (int i = tid; i < 2 * SROWS * 88; i += 256)
            (&ss->hbuf[0][0][0])[i] = __float2half(0.0f);
        for (int i = tid; i < 85 * 3; i += 256) {
            int v = i / 3, p = i % 3;
            ss->ebase[v][p] = __floats2half2_rn(base_emb[v * 6 + 2 * p], base_emb[v * 6 + 2 * p + 1]);
        }
        __syncthreads();
        if (tid < 32) ss->hbuf[tid >> 4][tid & 15][70] = __float2half(1.0f);
        if (tid < 48) {
            int r = tid / 3, p = tid % 3;
            *reinterpret_cast<__half2*>(&ss->hbuf[0][r][64 + 2 * p]) = ss->ebase[ss->tok[r][0]][p];
        }

        // persistent B fragments: gate g, k-tile kt (kt=4 = Wx|bias|0)
        unsigned bfr[4][5][2];
#pragma unroll
        for (int g = 0; g < 4; g++) {
            const int col = 64 * g + 8 * w + gid;
#pragma unroll
            for (int kt = 0; kt < 4; kt++) {
                int k0 = 16 * kt + 2 * tig;
                __half2 b0 = __floats2half2_rn(Wh[k0 * 256 + col], Wh[(k0 + 1) * 256 + col]);
                __half2 b1 = __floats2half2_rn(Wh[(k0 + 8) * 256 + col], Wh[(k0 + 9) * 256 + col]);
                bfr[g][kt][0] = *reinterpret_cast<unsigned*>(&b0);
                bfr[g][kt][1] = *reinterpret_cast<unsigned*>(&b1);
            }
            {
                int r0 = 64 + 2 * tig;
                float v0 = (r0 < 70) ? Wx[(r0 - 64) * 256 + col] : ((r0 == 70) ? bias[col] : 0.0f);
                float v1 = (r0 + 1 < 70) ? Wx[(r0 - 63) * 256 + col] : ((r0 + 1 == 70) ? bias[col] : 0.0f);
                __half2 b0 = __floats2half2_rn(v0, v1);
                bfr[g][4][0] = *reinterpret_cast<unsigned*>(&b0);
                bfr[g][4][1] = 0u;
            }
        }

        const int hc0 = 8 * w + 2 * tig;
        const int arow = (lane < 16) ? lane : (lane - 16);
        const int acol = (lane < 16) ? 0 : 8;
        const unsigned hb0 = (unsigned)__cvta_generic_to_shared(&ss->hbuf[0][arow][acol]);
        const unsigned hb1 = (unsigned)__cvta_generic_to_shared(&ss->hbuf[1][arow][acol]);

        float cst[4] = {0.0f, 0.0f, 0.0f, 0.0f};
        __syncthreads();

        for (int t = 0; t < LSQ; t++) {
            const unsigned hrd = (t & 1) ? hb1 : hb0;

            float d[4][4];
#pragma unroll
            for (int g = 0; g < 4; g++)
#pragma unroll
                for (int q = 0; q < 4; q++) d[g][q] = 0.0f;

#pragma unroll
            for (int kt = 0; kt < 5; kt++) {
                unsigned ah[4];
                asm volatile("ldmatrix.sync.aligned.m8n8.x4.shared.b16 {%0,%1,%2,%3}, [%4];\n"
                             : "=r"(ah[0]), "=r"(ah[1]), "=r"(ah[2]), "=r"(ah[3])
                             : "r"(hrd + kt * 32));
#pragma unroll
                for (int g = 0; g < 4; g++) {
                    asm("mma.sync.aligned.m16n8k16.row.col.f32.f16.f16.f32 "
                        "{%0,%1,%2,%3},{%4,%5,%6,%7},{%8,%9},{%0,%1,%2,%3};\n"
                        : "+f"(d[g][0]), "+f"(d[g][1]), "+f"(d[g][2]), "+f"(d[g][3])
                        : "r"(ah[0]), "r"(ah[1]), "r"(ah[2]), "r"(ah[3]),
                          "r"(bfr[g][kt][0]), "r"(bfr[g][kt][1]));
                }
            }

            float hv[4];
#pragma unroll
            for (int q = 0; q < 4; q++) {
                cst[q] = sig_hw(d[1][q]) * cst[q] + sig_hw(d[0][q]) * tanh_hw(d[2][q]);
                hv[q]  = sig_hw(d[3][q]) * tanh_hw(cst[q]);
            }

            const int wb = (t & 1) ^ 1;
            *reinterpret_cast<__half2*>(&ss->hbuf[wb][gid][hc0])     = __floats2half2_rn(hv[0], hv[1]);
            *reinterpret_cast<__half2*>(&ss->hbuf[wb][gid + 8][hc0]) = __floats2half2_rn(hv[2], hv[3]);
            if (t < LSQ - 1 && tid < 48) {
                int r = tid / 3, p = tid % 3;
                *reinterpret_cast<__half2*>(&ss->hbuf[wb][r][64 + 2 * p]) = ss->ebase[ss->tok[r][t + 1]][p];
            }

            if (t == LSQ - 1) {
                *reinterpret_cast<float2*>(&g_m[(row0 + gid) * 64 + hc0])     = make_float2(hv[0], hv[1]);
                *reinterpret_cast<float2*>(&g_m[(row0 + gid + 8) * 64 + hc0]) = make_float2(hv[2], hv[3]);
            }
            __syncthreads();
        }
    } else {
        // ---------------- nwf role: 11 list LSTMs (len 32, in 8, hid 8), scalar FMA ----------------
        NwfS* ns = reinterpret_cast<NwfS*>(sraw);
        const int bi = blockIdx.x - SEQ_CTAS;   // 0..175
        const int field = bi >> 4;              // 11 fields x 16 CTAs
        const int tile  = bi & 15;
        const int m = c_fm[field];
        const int row = tile * NWF_ROWS + tid;

        ns->wx[tid] = nWx_g[m * 256 + tid];
        ns->wh[tid] = nWh_g[m * 256 + tid];
        if (tid < 32) ns->bs[tid] = nb_g[m * 32 + tid];
        __syncthreads();

        const int* nrow = nums_g + (field * BATCH + row) * LN;
        const int* frow = frs_g + (field * BATCH + row) * LN;
        const float4* neg = reinterpret_cast<const float4*>(ne_g) + m * 1000;
        const float4* feg = reinterpret_cast<const float4*>(fe_g) + m * 1000;

        float h[8], c[8];
#pragma unroll
        for (int k = 0; k < 8; k++) { h[k] = 0.0f; c[k] = 0.0f; }

#define NWF_STEP(NI, FI) do {                                                      \
        float4 xn = __ldg(&neg[(NI)]);                                             \
        float4 xf = __ldg(&feg[(FI)]);                                             \
        float x[8] = {xn.x, xn.y, xn.z, xn.w, xf.x, xf.y, xf.z, xf.w};             \
        float acc[32];                                                             \
        _Pragma("unroll")                                                          \
        for (int j = 0; j < 32; j++) acc[j] = ns->bs[j];                           \
        _Pragma("unroll")                                                          \
        for (int k = 0; k < 8; k++) {                                              \
            _Pragma("unroll")                                                      \
            for (int j4 = 0; j4 < 8; j4++) {                                       \
                float4 wv = *reinterpret_cast<const float4*>(&ns->wx[k * 32 + j4 * 4]); \
                acc[4 * j4 + 0] = fmaf(x[k], wv.x, acc[4 * j4 + 0]);               \
                acc[4 * j4 + 1] = fmaf(x[k], wv.y, acc[4 * j4 + 1]);               \
                acc[4 * j4 + 2] = fmaf(x[k], wv.z, acc[4 * j4 + 2]);               \
                acc[4 * j4 + 3] = fmaf(x[k], wv.w, acc[4 * j4 + 3]);               \
            }                                                                      \
        }                                                                          \
        _Pragma("unroll")                                                          \
        for (int k = 0; k < 8; k++) {                                              \
            _Pragma("unroll")                                                      \
            for (int j4 = 0; j4 < 8; j4++) {                                       \
                float4 wv = *reinterpret_cast<const float4*>(&ns->wh[k * 32 + j4 * 4]); \
                acc[4 * j4 + 0] = fmaf(h[k], wv.x, acc[4 * j4 + 0]);               \
                acc[4 * j4 + 1] = fmaf(h[k], wv.y, acc[4 * j4 + 1]);               \
                acc[4 * j4 + 2] = fmaf(h[k], wv.z, acc[4 * j4 + 2]);               \
                acc[4 * j4 + 3] = fmaf(h[k], wv.w, acc[4 * j4 + 3]);               \
            }                                                                      \
        }                                                                          \
        _Pragma("unroll")                                                          \
        for (int k = 0; k < 8; k++) {                                              \
            c[k] = sig_hw(acc[8 + k]) * c[k] + sig_hw(acc[k]) * tanh_hw(acc[16 + k]); \
            h[k] = sig_hw(acc[24 + k]) * tanh_hw(c[k]);                            \
        }                                                                          \
    } while (0)

        for (int to = 0; to < LN; to += 4) {
            int4 nq = *reinterpret_cast<const int4*>(nrow + to);
            int4 fq = *reinterpret_cast<const int4*>(frow + to);
            NWF_STEP(nq.x, fq.x);
            NWF_STEP(nq.y, fq.y);
            NWF_STEP(nq.z, fq.z);
            NWF_STEP(nq.w, fq.w);
        }
#undef NWF_STEP

        float* o = &g_nwf[(field * BATCH + row) * 8];
#pragma unroll
        for (int k = 0; k < 8; k++) o[k] = h[k];
    }
}

// ---------------- kernel 2: feature concat + dense 234->64 + ReLU (2 outs/thread) ----------------
__global__ void __launch_bounds__(512) k_final(const float* __restrict__ goby_emb,
                                               const float* __restrict__ bool_emb,
                                               const float* __restrict__ count_emb,
                                               const float* __restrict__ W,
                                               const float* __restrict__ bias,
                                               const int* __restrict__ goby_idx,
                                               const int* __restrict__ is_indel,
                                               const int* __restrict__ matches_ref,
                                               const int* __restrict__ count_fwd,
                                               const int* __restrict__ count_rev,
                                               float* __restrict__ out) {
    const int tid = threadIdx.x;
    const int row0 = blockIdx.x * 16;
    __shared__ float fsh[16][240];

    for (int i = tid; i < 16 * 234; i += 512) {
        int rr = i / 234, f = i % 234;
        int row = row0 + rr;
        float v;
        if (f < 4)        v = goby_emb[goby_idx[row] * 4 + f];
        else if (f < 6)   v = bool_emb[is_indel[row] * 2 + (f - 4)];
        else if (f < 8)   v = bool_emb[matches_ref[row] * 2 + (f - 6)];
        else if (f < 72)  v = g_m[row * 64 + (f - 8)];
        else if (f < 136) v = g_m[(BATCH + row) * 64 + (f - 72)];
        else if (f < 141) v = count_emb[count_fwd[row] * 5 + (f - 136)];
        else if (f < 146) v = count_emb[count_rev[row] * 5 + (f - 141)];
        else {
            int ff = f - 146;
            v = g_nwf[((ff >> 3) * BATCH + row) * 8 + (ff & 7)];
        }
        fsh[rr][f] = v;
    }
    __syncthreads();

    const int o2 = tid & 31;   // column pair
    const int rr = tid >> 5;   // row 0..15
    const float2* W2 = reinterpret_cast<const float2*>(W);
    float2 acc = *reinterpret_cast<const float2*>(&bias[2 * o2]);
#pragma unroll 6
    for (int f = 0; f < 234; f++) {
        float v = fsh[rr][f];
        float2 wv = __ldg(&W2[f * 32 + o2]);
        acc.x = fmaf(v, wv.x, acc.x);
        acc.y = fmaf(v, wv.y, acc.y);
    }
    *reinterpret_cast<float2*>(&out[(row0 + rr) * 64 + 2 * o2]) =
        make_float2(fmaxf(acc.x, 0.0f), fmaxf(acc.y, 0.0f));
}

// ---------------- launch ----------------
extern "C" void kernel_launch(void* const* d_in, const int* in_sizes, int n_in,
                              void* d_out, int out_size) {
    static const int dictmap[23]  = {0,1,2,3,4,5,6,7,8,9,10,11,12,13,14,15,16,17,18,19,20,21,22};
    static const int parammap[23] = {14,15,16,17,18,19,20,21,22,0,1,2,3,4,5,6,7,8,9,10,11,12,13};
    const int* mp = (in_sizes[0] == BATCH) ? dictmap : parammap;

    const int*   goby_idx     = (const int*)  d_in[mp[0]];
    const int*   is_indel     = (const int*)  d_in[mp[1]];
    const int*   matches_ref  = (const int*)  d_in[mp[2]];
    const int*   from_seq     = (const int*)  d_in[mp[3]];
    const int*   to_seq       = (const int*)  d_in[mp[4]];
    const int*   count_fwd    = (const int*)  d_in[mp[5]];
    const int*   count_rev    = (const int*)  d_in[mp[6]];
    const int*   nwf_numbers  = (const int*)  d_in[mp[7]];
    const int*   nwf_freqs    = (const int*)  d_in[mp[8]];
    const float* goby_emb     = (const float*)d_in[mp[9]];
    const float* bool_emb     = (const float*)d_in[mp[10]];
    const float* count_emb    = (const float*)d_in[mp[11]];
    const float* base_emb     = (const float*)d_in[mp[12]];
    const float* seq_Wx       = (const float*)d_in[mp[13]];
    const float* seq_Wh       = (const float*)d_in[mp[14]];
    const float* seq_b        = (const float*)d_in[mp[15]];
    const float* nwf_num_emb  = (const float*)d_in[mp[16]];
    const float* nwf_freq_emb = (const float*)d_in[mp[17]];
    const float* nwf_Wx       = (const float*)d_in[mp[18]];
    const float* nwf_Wh       = (const float*)d_in[mp[19]];
    const float* nwf_b        = (const float*)d_in[mp[20]];
    const float* reduce_W     = (const float*)d_in[mp[21]];
    const float* reduce_b     = (const float*)d_in[mp[22]];

    k_main<<<SEQ_CTAS + NWF_CTAS, 256>>>(from_seq, to_seq, seq_Wh, seq_Wx, seq_b, base_emb,
                                         nwf_numbers, nwf_freqs, nwf_num_emb, nwf_freq_emb,
                                         nwf_Wx, nwf_Wh, nwf_b);
    k_final<<<BATCH / 16, 512>>>(goby_emb, bool_emb, count_emb, reduce_W, reduce_b,
                                 goby_idx, is_indel, matches_ref, count_fwd, count_rev,
                                 (float*)d_out);
}

// round 8
// speedup vs baseline: 4.3200x; 4.3200x over previous
#include <cuda_runtime.h>
#include <cuda_fp16.h>

#define BATCH 4096
#define LSQ   64
#define HID   64
#define NFLD  11
#define LN    32
#define SROWS 32   // rows per CTA in k_seq (two 16-row MMA tiles)

// ---------------- scratch (no allocations allowed) ----------------
__device__ float g_m[2 * BATCH * HID];      // [from rows 0..4095 | to rows 4096..8191] x 64
__device__ float g_nwf[NFLD * BATCH * 8];   // [11][4096][8]

__constant__ int c_fm[11] = {0, 0, 1, 1, 2, 2, 3, 3, 4, 5, 5};

__device__ __forceinline__ float tanh_hw(float x) {
    float y; asm("tanh.approx.f32 %0, %1;" : "=f"(y) : "f"(x)); return y;
}
__device__ __forceinline__ float sig_hw(float x) {
    return fmaf(tanh_hw(0.5f * x), 0.5f, 0.5f);
}

// ---------------- kernel 1: tensor-core sequence LSTM, x folded into MMA ----------------
// gates = [h(64) | emb(tok)(6) | 1 | 0...] @ [Wh ; Wx ; bias ; 0]  -> K=80, 5 k-tiles.
// 32 rows/CTA (two 16-row A tiles), 256 threads (8 warps). Warp w owns hidden
// cols [8w,8w+8) for all 4 gates on BOTH tiles -> 8 independent MMA chains/warp.
// occ 2 (128-reg budget, ~110 live, no spills); 256 CTAs = single wave.
__global__ void __launch_bounds__(256, 2) k_seq(const int* __restrict__ from_seq,
                                                const int* __restrict__ to_seq,
                                                const float* __restrict__ Wh,
                                                const float* __restrict__ Wx,
                                                const float* __restrict__ bias,
                                                const float* __restrict__ base_emb) {
    const int tid  = threadIdx.x;
    const int lane = tid & 31;
    const int w    = tid >> 5;    // warp 0..7 -> hidden cols [8w, 8w+8)
    const int gid  = lane >> 2;   // 0..7
    const int tig  = lane & 3;    // 0..3
    const int row0 = blockIdx.x * SROWS;   // in [0, 8192)

    __shared__ __half  hbuf[2][SROWS][88]; // cols 0-63 h, 64-69 emb, 70 = 1.0, 71-79 = 0
    __shared__ int     tok[SROWS][LSQ];
    __shared__ __half2 ebase[85][3];       // base_emb fp16, 3 half2 per vocab entry

    const int* seq = (row0 < BATCH) ? (from_seq + row0 * LSQ)
                                    : (to_seq + (row0 - BATCH) * LSQ);
    for (int i = tid; i < SROWS * LSQ; i += 256) tok[i >> 6][i & 63] = seq[i];
    for (int i = tid; i < 2 * SROWS * 88; i += 256)
        (&hbuf[0][0][0])[i] = __float2half(0.0f);
    for (int i = tid; i < 85 * 3; i += 256) {
        int v = i / 3, p = i % 3;
        ebase[v][p] = __floats2half2_rn(base_emb[v * 6 + 2 * p], base_emb[v * 6 + 2 * p + 1]);
    }
    __syncthreads();
    // specials: constant-1 column (both buffers), emb(tok_0) in buffer 0
    if (tid < 64) hbuf[tid >> 5][tid & 31][70] = __float2half(1.0f);
    if (tid < 96) {
        int r = tid / 3, p = tid % 3;
        *reinterpret_cast<__half2*>(&hbuf[0][r][64 + 2 * p]) = ebase[tok[r][0]][p];
    }

    // --- persistent B fragments (m16n8k16.row.col): gate g, k-tile kt (kt=4 = Wx|bias|0) ---
    unsigned bfr[4][5][2];
#pragma unroll
    for (int g = 0; g < 4; g++) {
        const int col = 64 * g + 8 * w + gid;
#pragma unroll
        for (int kt = 0; kt < 4; kt++) {
            int k0 = 16 * kt + 2 * tig;
            __half2 b0 = __floats2half2_rn(Wh[k0 * 256 + col], Wh[(k0 + 1) * 256 + col]);
            __half2 b1 = __floats2half2_rn(Wh[(k0 + 8) * 256 + col], Wh[(k0 + 9) * 256 + col]);
            bfr[g][kt][0] = *reinterpret_cast<unsigned*>(&b0);
            bfr[g][kt][1] = *reinterpret_cast<unsigned*>(&b1);
        }
        {   // kt=4: K rows 64..79 -> 64-69 Wx, 70 bias, 71-79 zero
            int r0 = 64 + 2 * tig;
            float v0 = (r0 < 70) ? Wx[(r0 - 64) * 256 + col] : ((r0 == 70) ? bias[col] : 0.0f);
            float v1 = (r0 + 1 < 70) ? Wx[(r0 - 63) * 256 + col] : ((r0 + 1 == 70) ? bias[col] : 0.0f);
            __half2 b0 = __floats2half2_rn(v0, v1);
            bfr[g][4][0] = *reinterpret_cast<unsigned*>(&b0);
            bfr[g][4][1] = 0u;   // rows 72..79 all zero
        }
    }

    const int hc0 = 8 * w + 2 * tig;      // this thread's hidden col pair

    // ldmatrix x4 source addressing: tile0 = rows 0-15, tile1 = rows 16-31
    const int arow = (lane < 16) ? lane : (lane - 16);
    const int acol = (lane < 16) ? 0 : 8;
    const unsigned a00 = (unsigned)__cvta_generic_to_shared(&hbuf[0][arow][acol]);
    const unsigned a01 = (unsigned)__cvta_generic_to_shared(&hbuf[0][16 + arow][acol]);
    const unsigned a10 = (unsigned)__cvta_generic_to_shared(&hbuf[1][arow][acol]);
    const unsigned a11 = (unsigned)__cvta_generic_to_shared(&hbuf[1][16 + arow][acol]);

    float cst[8] = {0.0f, 0.0f, 0.0f, 0.0f, 0.0f, 0.0f, 0.0f, 0.0f};

    __syncthreads();

    for (int t = 0; t < LSQ; t++) {
        const unsigned r0a = (t & 1) ? a10 : a00;
        const unsigned r1a = (t & 1) ? a11 : a01;

        float d0[4][4], d1[4][4];
#pragma unroll
        for (int g = 0; g < 4; g++)
#pragma unroll
            for (int q = 0; q < 4; q++) { d0[g][q] = 0.0f; d1[g][q] = 0.0f; }

#pragma unroll
        for (int kt = 0; kt < 5; kt++) {
            unsigned ah0[4], ah1[4];
            asm volatile("ldmatrix.sync.aligned.m8n8.x4.shared.b16 {%0,%1,%2,%3}, [%4];\n"
                         : "=r"(ah0[0]), "=r"(ah0[1]), "=r"(ah0[2]), "=r"(ah0[3])
                         : "r"(r0a + kt * 32));
            asm volatile("ldmatrix.sync.aligned.m8n8.x4.shared.b16 {%0,%1,%2,%3}, [%4];\n"
                         : "=r"(ah1[0]), "=r"(ah1[1]), "=r"(ah1[2]), "=r"(ah1[3])
                         : "r"(r1a + kt * 32));
#pragma unroll
            for (int g = 0; g < 4; g++) {
                asm("mma.sync.aligned.m16n8k16.row.col.f32.f16.f16.f32 "
                    "{%0,%1,%2,%3},{%4,%5,%6,%7},{%8,%9},{%0,%1,%2,%3};\n"
                    : "+f"(d0[g][0]), "+f"(d0[g][1]), "+f"(d0[g][2]), "+f"(d0[g][3])
                    : "r"(ah0[0]), "r"(ah0[1]), "r"(ah0[2]), "r"(ah0[3]),
                      "r"(bfr[g][kt][0]), "r"(bfr[g][kt][1]));
                asm("mma.sync.aligned.m16n8k16.row.col.f32.f16.f16.f32 "
                    "{%0,%1,%2,%3},{%4,%5,%6,%7},{%8,%9},{%0,%1,%2,%3};\n"
                    : "+f"(d1[g][0]), "+f"(d1[g][1]), "+f"(d1[g][2]), "+f"(d1[g][3])
                    : "r"(ah1[0]), "r"(ah1[1]), "r"(ah1[2]), "r"(ah1[3]),
                      "r"(bfr[g][kt][0]), "r"(bfr[g][kt][1]));
            }
        }

        // activations: 8 cells, all pre-activations complete (x + bias inside MMA)
        float hv[8];
#pragma unroll
        for (int q = 0; q < 4; q++) {
            cst[q] = sig_hw(d0[1][q]) * cst[q] + sig_hw(d0[0][q]) * tanh_hw(d0[2][q]);
            hv[q]  = sig_hw(d0[3][q]) * tanh_hw(cst[q]);
        }
#pragma unroll
        for (int q = 0; q < 4; q++) {
            cst[4 + q] = sig_hw(d1[1][q]) * cst[4 + q] + sig_hw(d1[0][q]) * tanh_hw(d1[2][q]);
            hv[4 + q]  = sig_hw(d1[3][q]) * tanh_hw(cst[4 + q]);
        }

        const int wb = (t & 1) ^ 1;
        *reinterpret_cast<__half2*>(&hbuf[wb][gid][hc0])      = __floats2half2_rn(hv[0], hv[1]);
        *reinterpret_cast<__half2*>(&hbuf[wb][gid + 8][hc0])  = __floats2half2_rn(hv[2], hv[3]);
        *reinterpret_cast<__half2*>(&hbuf[wb][gid + 16][hc0]) = __floats2half2_rn(hv[4], hv[5]);
        *reinterpret_cast<__half2*>(&hbuf[wb][gid + 24][hc0]) = __floats2half2_rn(hv[6], hv[7]);
        if (t < LSQ - 1 && tid < 96) {
            int r = tid / 3, p = tid % 3;
            *reinterpret_cast<__half2*>(&hbuf[wb][r][64 + 2 * p]) = ebase[tok[r][t + 1]][p];
        }

        if (t == LSQ - 1) {
            *reinterpret_cast<float2*>(&g_m[(row0 + gid) * 64 + hc0])      = make_float2(hv[0], hv[1]);
            *reinterpret_cast<float2*>(&g_m[(row0 + gid + 8) * 64 + hc0])  = make_float2(hv[2], hv[3]);
            *reinterpret_cast<float2*>(&g_m[(row0 + gid + 16) * 64 + hc0]) = make_float2(hv[4], hv[5]);
            *reinterpret_cast<float2*>(&g_m[(row0 + gid + 24) * 64 + hc0]) = make_float2(hv[6], hv[7]);
        }
        __syncthreads();
    }
}

// ---------------- kernel 2: 11 NWF list LSTMs (len 32, in 8, hid 8) ----------------
__global__ void __launch_bounds__(128) k_nwf(const int* __restrict__ nums_g,
                                             const int* __restrict__ frs_g,
                                             const float* __restrict__ ne_g,
                                             const float* __restrict__ fe_g,
                                             const float* __restrict__ Wx_g,
                                             const float* __restrict__ Wh_g,
                                             const float* __restrict__ b_g) {
    const int tid = threadIdx.x;
    const int field = blockIdx.y;
    const int m = c_fm[field];

    __shared__ alignas(16) float wx[8 * 32];
    __shared__ alignas(16) float wh[8 * 32];
    __shared__ float bs[32];
    __shared__ int ns[32][132];
    __shared__ int fs[32][132];

    for (int i = tid; i < 256; i += 128) {
        wx[i] = Wx_g[m * 256 + i];
        wh[i] = Wh_g[m * 256 + i];
    }
    if (tid < 32) bs[tid] = b_g[m * 32 + tid];

    const int base = field * BATCH * LN + blockIdx.x * 128 * LN;
    for (int i = tid; i < 128 * LN; i += 128) {
        int r = i >> 5, t = i & 31;
        ns[t][r] = nums_g[base + i];
        fs[t][r] = frs_g[base + i];
    }
    __syncthreads();

    const float4* neg = reinterpret_cast<const float4*>(ne_g) + m * 1000;
    const float4* feg = reinterpret_cast<const float4*>(fe_g) + m * 1000;

    float h[8], c[8];
#pragma unroll
    for (int k = 0; k < 8; k++) { h[k] = 0.0f; c[k] = 0.0f; }

    for (int t = 0; t < LN; t++) {
        float4 xn = __ldg(&neg[ns[t][tid]]);
        float4 xf = __ldg(&feg[fs[t][tid]]);
        float x[8] = {xn.x, xn.y, xn.z, xn.w, xf.x, xf.y, xf.z, xf.w};

        float acc[32];
#pragma unroll
        for (int j = 0; j < 32; j++) acc[j] = bs[j];

#pragma unroll
        for (int k = 0; k < 8; k++) {
#pragma unroll
            for (int j4 = 0; j4 < 8; j4++) {
                float4 wv = *reinterpret_cast<const float4*>(&wx[k * 32 + j4 * 4]);
                acc[4 * j4 + 0] = fmaf(x[k], wv.x, acc[4 * j4 + 0]);
                acc[4 * j4 + 1] = fmaf(x[k], wv.y, acc[4 * j4 + 1]);
                acc[4 * j4 + 2] = fmaf(x[k], wv.z, acc[4 * j4 + 2]);
                acc[4 * j4 + 3] = fmaf(x[k], wv.w, acc[4 * j4 + 3]);
            }
        }
#pragma unroll
        for (int k = 0; k < 8; k++) {
#pragma unroll
            for (int j4 = 0; j4 < 8; j4++) {
                float4 wv = *reinterpret_cast<const float4*>(&wh[k * 32 + j4 * 4]);
                acc[4 * j4 + 0] = fmaf(h[k], wv.x, acc[4 * j4 + 0]);
                acc[4 * j4 + 1] = fmaf(h[k], wv.y, acc[4 * j4 + 1]);
                acc[4 * j4 + 2] = fmaf(h[k], wv.z, acc[4 * j4 + 2]);
                acc[4 * j4 + 3] = fmaf(h[k], wv.w, acc[4 * j4 + 3]);
            }
        }
#pragma unroll
        for (int k = 0; k < 8; k++) {
            c[k] = sig_hw(acc[8 + k]) * c[k] + sig_hw(acc[k]) * tanh_hw(acc[16 + k]);
            h[k] = sig_hw(acc[24 + k]) * tanh_hw(c[k]);
        }
    }

    const int row = blockIdx.x * 128 + tid;
    float* o = &g_nwf[(field * BATCH + row) * 8];
#pragma unroll
    for (int k = 0; k < 8; k++) o[k] = h[k];
}

// ---------------- kernel 3: feature concat + dense 234->64 + ReLU ----------------
__global__ void __launch_bounds__(512) k_final(const float* __restrict__ goby_emb,
                                               const float* __restrict__ bool_emb,
                                               const float* __restrict__ count_emb,
                                               const float* __restrict__ W,
                                               const float* __restrict__ bias,
                                               const int* __restrict__ goby_idx,
                                               const int* __restrict__ is_indel,
                                               const int* __restrict__ matches_ref,
                                               const int* __restrict__ count_fwd,
                                               const int* __restrict__ count_rev,
                                               float* __restrict__ out) {
    const int tid = threadIdx.x;
    const int row0 = blockIdx.x * 8;
    __shared__ float fsh[8][240];

    for (int i = tid; i < 8 * 234; i += 512) {
        int rr = i / 234, f = i % 234;
        int row = row0 + rr;
        float v;
        if (f < 4)        v = goby_emb[goby_idx[row] * 4 + f];
        else if (f < 6)   v = bool_emb[is_indel[row] * 2 + (f - 4)];
        else if (f < 8)   v = bool_emb[matches_ref[row] * 2 + (f - 6)];
        else if (f < 72)  v = g_m[row * 64 + (f - 8)];
        else if (f < 136) v = g_m[(BATCH + row) * 64 + (f - 72)];
        else if (f < 141) v = count_emb[count_fwd[row] * 5 + (f - 136)];
        else if (f < 146) v = count_emb[count_rev[row] * 5 + (f - 141)];
        else {
            int ff = f - 146;
            v = g_nwf[((ff >> 3) * BATCH + row) * 8 + (ff & 7)];
        }
        fsh[rr][f] = v;
    }
    __syncthreads();

    const int o = tid & 63;
    const int rr = tid >> 6;
    float acc = bias[o];
#pragma unroll 6
    for (int f = 0; f < 234; f++)
        acc = fmaf(fsh[rr][f], __ldg(&W[f * 64 + o]), acc);
    out[(row0 + rr) * 64 + o] = fmaxf(acc, 0.0f);
}

// ---------------- launch ----------------
extern "C" void kernel_launch(void* const* d_in, const int* in_sizes, int n_in,
                              void* d_out, int out_size) {
    static const int dictmap[23]  = {0,1,2,3,4,5,6,7,8,9,10,11,12,13,14,15,16,17,18,19,20,21,22};
    static const int parammap[23] = {14,15,16,17,18,19,20,21,22,0,1,2,3,4,5,6,7,8,9,10,11,12,13};
    const int* mp = (in_sizes[0] == BATCH) ? dictmap : parammap;

    const int*   goby_idx     = (const int*)  d_in[mp[0]];
    const int*   is_indel     = (const int*)  d_in[mp[1]];
    const int*   matches_ref  = (const int*)  d_in[mp[2]];
    const int*   from_seq     = (const int*)  d_in[mp[3]];
    const int*   to_seq       = (const int*)  d_in[mp[4]];
    const int*   count_fwd    = (const int*)  d_in[mp[5]];
    const int*   count_rev    = (const int*)  d_in[mp[6]];
    const int*   nwf_numbers  = (const int*)  d_in[mp[7]];
    const int*   nwf_freqs    = (const int*)  d_in[mp[8]];
    const float* goby_emb     = (const float*)d_in[mp[9]];
    const float* bool_emb     = (const float*)d_in[mp[10]];
    const float* count_emb    = (const float*)d_in[mp[11]];
    const float* base_emb     = (const float*)d_in[mp[12]];
    const float* seq_Wx       = (const float*)d_in[mp[13]];
    const float* seq_Wh       = (const float*)d_in[mp[14]];
    const float* seq_b        = (const float*)d_in[mp[15]];
    const float* nwf_num_emb  = (const float*)d_in[mp[16]];
    const float* nwf_freq_emb = (const float*)d_in[mp[17]];
    const float* nwf_Wx       = (const float*)d_in[mp[18]];
    const float* nwf_Wh       = (const float*)d_in[mp[19]];
    const float* nwf_b        = (const float*)d_in[mp[20]];
    const float* reduce_W     = (const float*)d_in[mp[21]];
    const float* reduce_b     = (const float*)d_in[mp[22]];

    k_seq<<<(2 * BATCH) / SROWS, 256>>>(from_seq, to_seq, seq_Wh, seq_Wx, seq_b, base_emb);
    k_nwf<<<dim3(BATCH / 128, NFLD), 128>>>(nwf_numbers, nwf_freqs,
                                            nwf_num_emb, nwf_freq_emb,
                                            nwf_Wx, nwf_Wh, nwf_b);
    k_final<<<BATCH / 8, 512>>>(goby_emb, bool_emb, count_emb, reduce_W, reduce_b,
                                goby_idx, is_indel, matches_ref, count_fwd, count_rev,
                                (float*)d_out);
}

// round 9
// speedup vs baseline: 5.6678x; 1.3120x over previous
#include <cuda_runtime.h>
#include <cuda_fp16.h>

#define BATCH 4096
#define LSQ   64
#define HID   64
#define NFLD  11
#define LN    32
#define SROWS 32   // rows per CTA in k_seq (two 16-row MMA tiles)

// ---------------- scratch (no allocations allowed) ----------------
__device__ float g_m[2 * BATCH * HID];      // [from rows 0..4095 | to rows 4096..8191] x 64
__device__ float g_nwf[NFLD * BATCH * 8];   // [11][4096][8]

__constant__ int c_fm[11] = {0, 0, 1, 1, 2, 2, 3, 3, 4, 5, 5};

__device__ __forceinline__ float tanh_hw(float x) {
    float y; asm("tanh.approx.f32 %0, %1;" : "=f"(y) : "f"(x)); return y;
}
__device__ __forceinline__ float sig_hw(float x) {
    return fmaf(tanh_hw(0.5f * x), 0.5f, 0.5f);
}

// ---------------- kernel 1: tensor-core sequence LSTM (unchanged from R8) ----------------
__global__ void __launch_bounds__(256, 2) k_seq(const int* __restrict__ from_seq,
                                                const int* __restrict__ to_seq,
                                                const float* __restrict__ Wh,
                                                const float* __restrict__ Wx,
                                                const float* __restrict__ bias,
                                                const float* __restrict__ base_emb) {
    const int tid  = threadIdx.x;
    const int lane = tid & 31;
    const int w    = tid >> 5;
    const int gid  = lane >> 2;
    const int tig  = lane & 3;
    const int row0 = blockIdx.x * SROWS;

    __shared__ __half  hbuf[2][SROWS][88];
    __shared__ int     tok[SROWS][LSQ];
    __shared__ __half2 ebase[85][3];

    const int* seq = (row0 < BATCH) ? (from_seq + row0 * LSQ)
                                    : (to_seq + (row0 - BATCH) * LSQ);
    for (int i = tid; i < SROWS * LSQ; i += 256) tok[i >> 6][i & 63] = seq[i];
    for (int i = tid; i < 2 * SROWS * 88; i += 256)
        (&hbuf[0][0][0])[i] = __float2half(0.0f);
    for (int i = tid; i < 85 * 3; i += 256) {
        int v = i / 3, p = i % 3;
        ebase[v][p] = __floats2half2_rn(base_emb[v * 6 + 2 * p], base_emb[v * 6 + 2 * p + 1]);
    }
    __syncthreads();
    if (tid < 64) hbuf[tid >> 5][tid & 31][70] = __float2half(1.0f);
    if (tid < 96) {
        int r = tid / 3, p = tid % 3;
        *reinterpret_cast<__half2*>(&hbuf[0][r][64 + 2 * p]) = ebase[tok[r][0]][p];
    }

    unsigned bfr[4][5][2];
#pragma unroll
    for (int g = 0; g < 4; g++) {
        const int col = 64 * g + 8 * w + gid;
#pragma unroll
        for (int kt = 0; kt < 4; kt++) {
            int k0 = 16 * kt + 2 * tig;
            __half2 b0 = __floats2half2_rn(Wh[k0 * 256 + col], Wh[(k0 + 1) * 256 + col]);
            __half2 b1 = __floats2half2_rn(Wh[(k0 + 8) * 256 + col], Wh[(k0 + 9) * 256 + col]);
            bfr[g][kt][0] = *reinterpret_cast<unsigned*>(&b0);
            bfr[g][kt][1] = *reinterpret_cast<unsigned*>(&b1);
        }
        {
            int r0 = 64 + 2 * tig;
            float v0 = (r0 < 70) ? Wx[(r0 - 64) * 256 + col] : ((r0 == 70) ? bias[col] : 0.0f);
            float v1 = (r0 + 1 < 70) ? Wx[(r0 - 63) * 256 + col] : ((r0 + 1 == 70) ? bias[col] : 0.0f);
            __half2 b0 = __floats2half2_rn(v0, v1);
            bfr[g][4][0] = *reinterpret_cast<unsigned*>(&b0);
            bfr[g][4][1] = 0u;
        }
    }

    const int hc0 = 8 * w + 2 * tig;
    const int arow = (lane < 16) ? lane : (lane - 16);
    const int acol = (lane < 16) ? 0 : 8;
    const unsigned a00 = (unsigned)__cvta_generic_to_shared(&hbuf[0][arow][acol]);
    const unsigned a01 = (unsigned)__cvta_generic_to_shared(&hbuf[0][16 + arow][acol]);
    const unsigned a10 = (unsigned)__cvta_generic_to_shared(&hbuf[1][arow][acol]);
    const unsigned a11 = (unsigned)__cvta_generic_to_shared(&hbuf[1][16 + arow][acol]);

    float cst[8] = {0.0f, 0.0f, 0.0f, 0.0f, 0.0f, 0.0f, 0.0f, 0.0f};

    __syncthreads();

    for (int t = 0; t < LSQ; t++) {
        const unsigned r0a = (t & 1) ? a10 : a00;
        const unsigned r1a = (t & 1) ? a11 : a01;

        float d0[4][4], d1[4][4];
#pragma unroll
        for (int g = 0; g < 4; g++)
#pragma unroll
            for (int q = 0; q < 4; q++) { d0[g][q] = 0.0f; d1[g][q] = 0.0f; }

#pragma unroll
        for (int kt = 0; kt < 5; kt++) {
            unsigned ah0[4], ah1[4];
            asm volatile("ldmatrix.sync.aligned.m8n8.x4.shared.b16 {%0,%1,%2,%3}, [%4];\n"
                         : "=r"(ah0[0]), "=r"(ah0[1]), "=r"(ah0[2]), "=r"(ah0[3])
                         : "r"(r0a + kt * 32));
            asm volatile("ldmatrix.sync.aligned.m8n8.x4.shared.b16 {%0,%1,%2,%3}, [%4];\n"
                         : "=r"(ah1[0]), "=r"(ah1[1]), "=r"(ah1[2]), "=r"(ah1[3])
                         : "r"(r1a + kt * 32));
#pragma unroll
            for (int g = 0; g < 4; g++) {
                asm("mma.sync.aligned.m16n8k16.row.col.f32.f16.f16.f32 "
                    "{%0,%1,%2,%3},{%4,%5,%6,%7},{%8,%9},{%0,%1,%2,%3};\n"
                    : "+f"(d0[g][0]), "+f"(d0[g][1]), "+f"(d0[g][2]), "+f"(d0[g][3])
                    : "r"(ah0[0]), "r"(ah0[1]), "r"(ah0[2]), "r"(ah0[3]),
                      "r"(bfr[g][kt][0]), "r"(bfr[g][kt][1]));
                asm("mma.sync.aligned.m16n8k16.row.col.f32.f16.f16.f32 "
                    "{%0,%1,%2,%3},{%4,%5,%6,%7},{%8,%9},{%0,%1,%2,%3};\n"
                    : "+f"(d1[g][0]), "+f"(d1[g][1]), "+f"(d1[g][2]), "+f"(d1[g][3])
                    : "r"(ah1[0]), "r"(ah1[1]), "r"(ah1[2]), "r"(ah1[3]),
                      "r"(bfr[g][kt][0]), "r"(bfr[g][kt][1]));
            }
        }

        float hv[8];
#pragma unroll
        for (int q = 0; q < 4; q++) {
            cst[q] = sig_hw(d0[1][q]) * cst[q] + sig_hw(d0[0][q]) * tanh_hw(d0[2][q]);
            hv[q]  = sig_hw(d0[3][q]) * tanh_hw(cst[q]);
        }
#pragma unroll
        for (int q = 0; q < 4; q++) {
            cst[4 + q] = sig_hw(d1[1][q]) * cst[4 + q] + sig_hw(d1[0][q]) * tanh_hw(d1[2][q]);
            hv[4 + q]  = sig_hw(d1[3][q]) * tanh_hw(cst[4 + q]);
        }

        const int wb = (t & 1) ^ 1;
        *reinterpret_cast<__half2*>(&hbuf[wb][gid][hc0])      = __floats2half2_rn(hv[0], hv[1]);
        *reinterpret_cast<__half2*>(&hbuf[wb][gid + 8][hc0])  = __floats2half2_rn(hv[2], hv[3]);
        *reinterpret_cast<__half2*>(&hbuf[wb][gid + 16][hc0]) = __floats2half2_rn(hv[4], hv[5]);
        *reinterpret_cast<__half2*>(&hbuf[wb][gid + 24][hc0]) = __floats2half2_rn(hv[6], hv[7]);
        if (t < LSQ - 1 && tid < 96) {
            int r = tid / 3, p = tid % 3;
            *reinterpret_cast<__half2*>(&hbuf[wb][r][64 + 2 * p]) = ebase[tok[r][t + 1]][p];
        }

        if (t == LSQ - 1) {
            *reinterpret_cast<float2*>(&g_m[(row0 + gid) * 64 + hc0])      = make_float2(hv[0], hv[1]);
            *reinterpret_cast<float2*>(&g_m[(row0 + gid + 8) * 64 + hc0])  = make_float2(hv[2], hv[3]);
            *reinterpret_cast<float2*>(&g_m[(row0 + gid + 16) * 64 + hc0]) = make_float2(hv[4], hv[5]);
            *reinterpret_cast<float2*>(&g_m[(row0 + gid + 24) * 64 + hc0]) = make_float2(hv[6], hv[7]);
        }
        __syncthreads();
    }
}

// ---------------- kernel 2: tensor-core NWF LSTMs ----------------
// gates[16 rows][32] = [x(8)|h(8)] @ [Wx;Wh] : one m16n8k16 per gate tile.
// Warp = 16 rows of one field; no CTA barrier in the loop (warp-independent).
// CTA = 256 threads = 8 warps = 128 rows. grid = (4096/128, 11).
__global__ void __launch_bounds__(256, 2) k_nwf(const int* __restrict__ nums_g,
                                                const int* __restrict__ frs_g,
                                                const float* __restrict__ ne_g,
                                                const float* __restrict__ fe_g,
                                                const float* __restrict__ Wx_g,
                                                const float* __restrict__ Wh_g,
                                                const float* __restrict__ b_g) {
    const int tid  = threadIdx.x;
    const int lane = tid & 31;
    const int w    = tid >> 5;
    const int gid  = lane >> 2;
    const int tig  = lane & 3;
    const int field = blockIdx.y;
    const int m = c_fm[field];
    const int row0 = blockIdx.x * 128;

    __shared__ int    ns[LN][132];           // [t][row] transposed staging
    __shared__ int    fs[LN][132];
    __shared__ __half At[8][16][24];         // per-warp A tile: cols 0-7 x, 8-15 h; stride 24 (ldsm conflict-free)

    const int base = (field * BATCH + row0) * LN;
    for (int i = tid; i < 128 * LN; i += 256) {
        int r = i >> 5, t = i & 31;
        ns[t][r] = nums_g[base + i];
        fs[t][r] = frs_g[base + i];
    }
    for (int i = tid; i < 8 * 16 * 24 / 2; i += 256)
        reinterpret_cast<__half2*>(&At[0][0][0])[i] = __floats2half2_rn(0.0f, 0.0f);
    __syncthreads();

    // persistent B fragments: n-tile g = gate g (cols 8g..8g+7). K rows 0-7 = Wx, 8-15 = Wh.
    unsigned bf[4][2];
    float2 b2[4];
#pragma unroll
    for (int g = 0; g < 4; g++) {
        const int col = 8 * g + gid;
        __half2 x0 = __floats2half2_rn(Wx_g[m * 256 + (2 * tig) * 32 + col],
                                       Wx_g[m * 256 + (2 * tig + 1) * 32 + col]);
        __half2 h0 = __floats2half2_rn(Wh_g[m * 256 + (2 * tig) * 32 + col],
                                       Wh_g[m * 256 + (2 * tig + 1) * 32 + col]);
        bf[g][0] = *reinterpret_cast<unsigned*>(&x0);
        bf[g][1] = *reinterpret_cast<unsigned*>(&h0);
        b2[g] = make_float2(b_g[m * 32 + 8 * g + 2 * tig], b_g[m * 32 + 8 * g + 2 * tig + 1]);
    }

    const float4* neg = reinterpret_cast<const float4*>(ne_g) + m * 1000;
    const float4* feg = reinterpret_cast<const float4*>(fe_g) + m * 1000;

    const int lrow = lane & 15;              // row within warp tile for gather/ldsm
    const bool isNe = (lane < 16);
    const int myrow = w * 16 + lrow;         // column in staged index arrays
    const int xcol = isNe ? 0 : 4;
    const unsigned aaddr = (unsigned)__cvta_generic_to_shared(&At[w][lrow][isNe ? 0 : 8]);

    float cst[4] = {0.0f, 0.0f, 0.0f, 0.0f};
    float hv[4] = {0.0f, 0.0f, 0.0f, 0.0f};

    for (int t = 0; t < LN; t++) {
        // x gather: lanes 0-15 ne for their row, lanes 16-31 fe
        int idx = isNe ? ns[t][myrow] : fs[t][myrow];
        float4 v = __ldg(isNe ? &neg[idx] : &feg[idx]);
        *reinterpret_cast<__half2*>(&At[w][lrow][xcol])     = __floats2half2_rn(v.x, v.y);
        *reinterpret_cast<__half2*>(&At[w][lrow][xcol + 2]) = __floats2half2_rn(v.z, v.w);
        __syncwarp();   // x of step t + h of step t-1 visible warp-wide

        unsigned a[4];
        asm volatile("ldmatrix.sync.aligned.m8n8.x4.shared.b16 {%0,%1,%2,%3}, [%4];\n"
                     : "=r"(a[0]), "=r"(a[1]), "=r"(a[2]), "=r"(a[3]) : "r"(aaddr));

        float d[4][4];
#pragma unroll
        for (int g = 0; g < 4; g++) {
            d[g][0] = 0.0f; d[g][1] = 0.0f; d[g][2] = 0.0f; d[g][3] = 0.0f;
            asm("mma.sync.aligned.m16n8k16.row.col.f32.f16.f16.f32 "
                "{%0,%1,%2,%3},{%4,%5,%6,%7},{%8,%9},{%0,%1,%2,%3};\n"
                : "+f"(d[g][0]), "+f"(d[g][1]), "+f"(d[g][2]), "+f"(d[g][3])
                : "r"(a[0]), "r"(a[1]), "r"(a[2]), "r"(a[3]),
                  "r"(bf[g][0]), "r"(bf[g][1]));
        }

        // cells: (gid,2tig),(gid,2tig+1),(gid+8,2tig),(gid+8,2tig+1)
#pragma unroll
        for (int q = 0; q < 4; q++) {
            float bi = (q & 1) ? b2[0].y : b2[0].x;
            float bff = (q & 1) ? b2[1].y : b2[1].x;
            float bgg = (q & 1) ? b2[2].y : b2[2].x;
            float bo = (q & 1) ? b2[3].y : b2[3].x;
            float gi = d[0][q] + bi, gf = d[1][q] + bff, gg = d[2][q] + bgg, go = d[3][q] + bo;
            cst[q] = sig_hw(gf) * cst[q] + sig_hw(gi) * tanh_hw(gg);
            hv[q]  = sig_hw(go) * tanh_hw(cst[q]);
        }

        // h write-back (fp16) into A cols 8-15; next iteration's syncwarp orders it
        *reinterpret_cast<__half2*>(&At[w][gid][8 + 2 * tig])     = __floats2half2_rn(hv[0], hv[1]);
        *reinterpret_cast<__half2*>(&At[w][gid + 8][8 + 2 * tig]) = __floats2half2_rn(hv[2], hv[3]);
    }

    float* o = &g_nwf[(field * BATCH + row0 + w * 16) * 8];
    *reinterpret_cast<float2*>(&o[gid * 8 + 2 * tig])       = make_float2(hv[0], hv[1]);
    *reinterpret_cast<float2*>(&o[(gid + 8) * 8 + 2 * tig]) = make_float2(hv[2], hv[3]);
}

// ---------------- kernel 3: feature concat + dense 234->64 + ReLU ----------------
__global__ void __launch_bounds__(512) k_final(const float* __restrict__ goby_emb,
                                               const float* __restrict__ bool_emb,
                                               const float* __restrict__ count_emb,
                                               const float* __restrict__ W,
                                               const float* __restrict__ bias,
                                               const int* __restrict__ goby_idx,
                                               const int* __restrict__ is_indel,
                                               const int* __restrict__ matches_ref,
                                               const int* __restrict__ count_fwd,
                                               const int* __restrict__ count_rev,
                                               float* __restrict__ out) {
    const int tid = threadIdx.x;
    const int row0 = blockIdx.x * 8;
    __shared__ float fsh[8][240];

    for (int i = tid; i < 8 * 234; i += 512) {
        int rr = i / 234, f = i % 234;
        int row = row0 + rr;
        float v;
        if (f < 4)        v = goby_emb[goby_idx[row] * 4 + f];
        else if (f < 6)   v = bool_emb[is_indel[row] * 2 + (f - 4)];
        else if (f < 8)   v = bool_emb[matches_ref[row] * 2 + (f - 6)];
        else if (f < 72)  v = g_m[row * 64 + (f - 8)];
        else if (f < 136) v = g_m[(BATCH + row) * 64 + (f - 72)];
        else if (f < 141) v = count_emb[count_fwd[row] * 5 + (f - 136)];
        else if (f < 146) v = count_emb[count_rev[row] * 5 + (f - 141)];
        else {
            int ff = f - 146;
            v = g_nwf[((ff >> 3) * BATCH + row) * 8 + (ff & 7)];
        }
        fsh[rr][f] = v;
    }
    __syncthreads();

    const int o = tid & 63;
    const int rr = tid >> 6;
    float acc = bias[o];
#pragma unroll 6
    for (int f = 0; f < 234; f++)
        acc = fmaf(fsh[rr][f], __ldg(&W[f * 64 + o]), acc);
    out[(row0 + rr) * 64 + o] = fmaxf(acc, 0.0f);
}

// ---------------- launch ----------------
extern "C" void kernel_launch(void* const* d_in, const int* in_sizes, int n_in,
                              void* d_out, int out_size) {
    static const int dictmap[23]  = {0,1,2,3,4,5,6,7,8,9,10,11,12,13,14,15,16,17,18,19,20,21,22};
    static const int parammap[23] = {14,15,16,17,18,19,20,21,22,0,1,2,3,4,5,6,7,8,9,10,11,12,13};
    const int* mp = (in_sizes[0] == BATCH) ? dictmap : parammap;

    const int*   goby_idx     = (const int*)  d_in[mp[0]];
    const int*   is_indel     = (const int*)  d_in[mp[1]];
    const int*   matches_ref  = (const int*)  d_in[mp[2]];
    const int*   from_seq     = (const int*)  d_in[mp[3]];
    const int*   to_seq       = (const int*)  d_in[mp[4]];
    const int*   count_fwd    = (const int*)  d_in[mp[5]];
    const int*   count_rev    = (const int*)  d_in[mp[6]];
    const int*   nwf_numbers  = (const int*)  d_in[mp[7]];
    const int*   nwf_freqs    = (const int*)  d_in[mp[8]];
    const float* goby_emb     = (const float*)d_in[mp[9]];
    const float* bool_emb     = (const float*)d_in[mp[10]];
    const float* count_emb    = (const float*)d_in[mp[11]];
    const float* base_emb     = (const float*)d_in[mp[12]];
    const float* seq_Wx       = (const float*)d_in[mp[13]];
    const float* seq_Wh       = (const float*)d_in[mp[14]];
    const float* seq_b        = (const float*)d_in[mp[15]];
    const float* nwf_num_emb  = (const float*)d_in[mp[16]];
    const float* nwf_freq_emb = (const float*)d_in[mp[17]];
    const float* nwf_Wx       = (const float*)d_in[mp[18]];
    const float* nwf_Wh       = (const float*)d_in[mp[19]];
    const float* nwf_b        = (const float*)d_in[mp[20]];
    const float* reduce_W     = (const float*)d_in[mp[21]];
    const float* reduce_b     = (const float*)d_in[mp[22]];

    k_seq<<<(2 * BATCH) / SROWS, 256>>>(from_seq, to_seq, seq_Wh, seq_Wx, seq_b, base_emb);
    k_nwf<<<dim3(BATCH / 128, NFLD), 256>>>(nwf_numbers, nwf_freqs,
                                            nwf_num_emb, nwf_freq_emb,
                                            nwf_Wx, nwf_Wh, nwf_b);
    k_final<<<BATCH / 8, 512>>>(goby_emb, bool_emb, count_emb, reduce_W, reduce_b,
                                goby_idx, is_indel, matches_ref, count_fwd, count_rev,
                                (float*)d_out);
}